// round 2
// baseline (speedup 1.0000x reference)
#include <cuda_runtime.h>
#include <math.h>

// Problem constants (B=4, S=2048 -> T=8192; D=1024; H=2048; E=8; topk=2)
#define T_TOK 8192
#define DDIM  1024
#define HDIM  2048
#define NEXP  8
#define MAXSLOTS (T_TOK * 2)   // every token occupies exactly 2 slots

// ---------------- static device scratch (no cudaMalloc allowed) ----------------
__device__ int   g_cnt[NEXP];
__device__ int   g_cur[NEXP];
__device__ int   g_off[NEXP + 1];
__device__ int   g_texp[T_TOK * 2];     // (token,k) -> expert
__device__ float g_twt [T_TOK * 2];     // (token,k) -> softmax weight
__device__ int   g_tok [MAXSLOTS];      // slot -> token
__device__ float g_wt  [MAXSLOTS];      // slot -> weight
__device__ int   g_slot[T_TOK * 2];     // (token,k) -> slot
__device__ float g_h1[(size_t)MAXSLOTS * HDIM];   // 128 MB
__device__ float g_h2[(size_t)MAXSLOTS * HDIM];   // 128 MB
__device__ float g_ys[(size_t)MAXSLOTS * DDIM];   //  64 MB

// ---------------- init: zero per-expert counters (must run every replay) -------
__global__ void k_init() {
    if (threadIdx.x < NEXP) g_cnt[threadIdx.x] = 0;
}

// ---------------- gating: one warp per token ----------------------------------
__global__ void k_gate(const float* __restrict__ x, const float* __restrict__ gw) {
    int warp = (blockIdx.x * blockDim.x + threadIdx.x) >> 5;
    int lane = threadIdx.x & 31;
    if (warp >= T_TOK) return;
    const float* xr = x + (size_t)warp * DDIM;

    float xv[32];
#pragma unroll
    for (int j = 0; j < 32; j++) xv[j] = xr[j * 32 + lane];

    float lg[NEXP];
#pragma unroll
    for (int e = 0; e < NEXP; e++) {
        const float* g = gw + e * DDIM;
        float s = 0.f;
#pragma unroll
        for (int j = 0; j < 32; j++) s += xv[j] * g[j * 32 + lane];
#pragma unroll
        for (int d = 16; d > 0; d >>= 1) s += __shfl_xor_sync(0xffffffffu, s, d);
        lg[e] = s;   // all lanes hold the full logit
    }

    // top-2 (ties -> lower index, matching jax.lax.top_k)
    int e0 = 0; float v0 = lg[0];
#pragma unroll
    for (int e = 1; e < NEXP; e++) if (lg[e] > v0) { v0 = lg[e]; e0 = e; }
    int e1 = (e0 == 0) ? 1 : 0; float v1 = lg[e1];
#pragma unroll
    for (int e = 0; e < NEXP; e++)
        if (e != e0 && lg[e] > v1) { v1 = lg[e]; e1 = e; }

    float w0 = 1.f / (1.f + expf(v1 - v0));   // softmax over (v0, v1), v0 >= v1
    float w1 = 1.f - w0;

    if (lane == 0) {
        atomicAdd(&g_cnt[e0], 1);
        atomicAdd(&g_cnt[e1], 1);
        g_texp[warp * 2 + 0] = e0;  g_texp[warp * 2 + 1] = e1;
        g_twt [warp * 2 + 0] = w0;  g_twt [warp * 2 + 1] = w1;
    }
}

// ---------------- prefix sum over 8 experts ------------------------------------
__global__ void k_prefix() {
    int s = 0;
    for (int e = 0; e < NEXP; e++) { g_off[e] = s; g_cur[e] = s; s += g_cnt[e]; }
    g_off[NEXP] = s;
}

// ---------------- scatter tokens into compact per-expert slot ranges -----------
__global__ void k_scatter() {
    int t = blockIdx.x * blockDim.x + threadIdx.x;
    if (t >= T_TOK) return;
#pragma unroll
    for (int k = 0; k < 2; k++) {
        int e = g_texp[t * 2 + k];
        int s = atomicAdd(&g_cur[e], 1);       // cur starts at off[e]
        g_tok[s] = t;
        g_wt[s]  = g_twt[t * 2 + k];
        g_slot[t * 2 + k] = s;
    }
}

// ---------------- GEMM 1/2: dst[slot,n] = gatherX[slot,:] @ W[e][n,:] + B[e][n] -
// C tile 128x128, K step 16, 256 threads, 8x8 microtile.
// DST selects the __device__ global destination (0 -> g_h1, 1 -> g_h2);
// device globals must NOT be passed as kernel args from host code.
template<int DST>
__global__ void __launch_bounds__(256) k_gemm_gather(
    const float* __restrict__ X,     // [T, Kd]
    const float* __restrict__ W,     // [E, Nd, Kd]
    const float* __restrict__ B,     // [E, Nd]
    int Kd, int Nd)
{
    float* dst = (DST == 0) ? g_h1 : g_h2;

    int e   = blockIdx.z;
    int cnt = g_cnt[e];
    int m0  = blockIdx.y * 128;
    if (m0 >= cnt) return;
    int off = g_off[e];
    int n0  = blockIdx.x * 128;
    const float* We = W + (size_t)e * Nd * Kd;
    const float* Be = B + (size_t)e * Nd;

    __shared__ float As[16][128];
    __shared__ float Bs[16][128];
    __shared__ int   toks[128];

    int tid = threadIdx.x;
    if (tid < 128) {
        int r = m0 + tid;
        toks[tid] = g_tok[off + (r < cnt ? r : 0)];
    }
    __syncthreads();

    float acc[8][8];
#pragma unroll
    for (int i = 0; i < 8; i++)
#pragma unroll
        for (int j = 0; j < 8; j++) acc[i][j] = 0.f;

    int ty = tid >> 4, tx = tid & 15;

    for (int k0 = 0; k0 < Kd; k0 += 16) {
#pragma unroll
        for (int l = 0; l < 2; l++) {
            int idx = tid + l * 256;
            int row = idx >> 2, c4 = idx & 3;
            float4 va = *(const float4*)(X  + (size_t)toks[row] * Kd + k0 + c4 * 4);
            As[c4 * 4 + 0][row] = va.x; As[c4 * 4 + 1][row] = va.y;
            As[c4 * 4 + 2][row] = va.z; As[c4 * 4 + 3][row] = va.w;
            float4 vb = *(const float4*)(We + (size_t)(n0 + row) * Kd + k0 + c4 * 4);
            Bs[c4 * 4 + 0][row] = vb.x; Bs[c4 * 4 + 1][row] = vb.y;
            Bs[c4 * 4 + 2][row] = vb.z; Bs[c4 * 4 + 3][row] = vb.w;
        }
        __syncthreads();
#pragma unroll
        for (int kk = 0; kk < 16; kk++) {
            float a[8], b[8];
#pragma unroll
            for (int i = 0; i < 8; i++) a[i] = As[kk][ty * 8 + i];
#pragma unroll
            for (int j = 0; j < 8; j++) b[j] = Bs[kk][tx * 8 + j];
#pragma unroll
            for (int i = 0; i < 8; i++)
#pragma unroll
                for (int j = 0; j < 8; j++) acc[i][j] += a[i] * b[j];
        }
        __syncthreads();
    }

#pragma unroll
    for (int i = 0; i < 8; i++) {
        int r = m0 + ty * 8 + i;
        if (r < cnt) {
            float* drow = dst + (size_t)(off + r) * Nd + n0 + tx * 8;
#pragma unroll
            for (int j = 0; j < 8; j++)
                drow[j] = acc[i][j] + Be[n0 + tx * 8 + j];
        }
    }
}

// ---------------- elementwise: h1 = h1 * silu(h2) ------------------------------
__global__ void k_act() {
    size_t i = (size_t)blockIdx.x * blockDim.x + threadIdx.x;   // float4 index
    if (i >= (size_t)MAXSLOTS * (HDIM / 4)) return;
    float4 a = ((const float4*)g_h1)[i];
    float4 b = ((const float4*)g_h2)[i];
    a.x *= b.x / (1.f + expf(-b.x));
    a.y *= b.y / (1.f + expf(-b.y));
    a.z *= b.z / (1.f + expf(-b.z));
    a.w *= b.w / (1.f + expf(-b.w));
    ((float4*)g_h1)[i] = a;
}

// ---------------- GEMM 3: ys[slot,n] = wt[slot] * (h1[slot,:] @ w3[e][n,:] + b3) -
__global__ void __launch_bounds__(256) k_gemm_slab(
    const float* __restrict__ W,     // w3: [E, Nd=D, Kd=H]
    const float* __restrict__ B)     // b3: [E, D]
{
    const int Kd = HDIM, Nd = DDIM;
    int e   = blockIdx.z;
    int cnt = g_cnt[e];
    int m0  = blockIdx.y * 128;
    if (m0 >= cnt) return;
    int off = g_off[e];
    int n0  = blockIdx.x * 128;
    const float* We = W + (size_t)e * Nd * Kd;
    const float* Be = B + (size_t)e * Nd;

    __shared__ float As[16][128];
    __shared__ float Bs[16][128];

    int tid = threadIdx.x;
    int ty = tid >> 4, tx = tid & 15;

    float acc[8][8];
#pragma unroll
    for (int i = 0; i < 8; i++)
#pragma unroll
        for (int j = 0; j < 8; j++) acc[i][j] = 0.f;

    for (int k0 = 0; k0 < Kd; k0 += 16) {
#pragma unroll
        for (int l = 0; l < 2; l++) {
            int idx = tid + l * 256;
            int row = idx >> 2, c4 = idx & 3;
            int r = m0 + row;
            int arow = off + (r < cnt ? r : m0);
            float4 va = *(const float4*)(g_h1 + (size_t)arow * Kd + k0 + c4 * 4);
            As[c4 * 4 + 0][row] = va.x; As[c4 * 4 + 1][row] = va.y;
            As[c4 * 4 + 2][row] = va.z; As[c4 * 4 + 3][row] = va.w;
            float4 vb = *(const float4*)(We + (size_t)(n0 + row) * Kd + k0 + c4 * 4);
            Bs[c4 * 4 + 0][row] = vb.x; Bs[c4 * 4 + 1][row] = vb.y;
            Bs[c4 * 4 + 2][row] = vb.z; Bs[c4 * 4 + 3][row] = vb.w;
        }
        __syncthreads();
#pragma unroll
        for (int kk = 0; kk < 16; kk++) {
            float a[8], b[8];
#pragma unroll
            for (int i = 0; i < 8; i++) a[i] = As[kk][ty * 8 + i];
#pragma unroll
            for (int j = 0; j < 8; j++) b[j] = Bs[kk][tx * 8 + j];
#pragma unroll
            for (int i = 0; i < 8; i++)
#pragma unroll
                for (int j = 0; j < 8; j++) acc[i][j] += a[i] * b[j];
        }
        __syncthreads();
    }

#pragma unroll
    for (int i = 0; i < 8; i++) {
        int r = m0 + ty * 8 + i;
        if (r < cnt) {
            int slot = off + r;
            float w = g_wt[slot];
            float* drow = g_ys + (size_t)slot * Nd + n0 + tx * 8;
#pragma unroll
            for (int j = 0; j < 8; j++)
                drow[j] = w * (acc[i][j] + Be[n0 + tx * 8 + j]);
        }
    }
}

// ---------------- combine: out[t] = ys[slot0(t)] + ys[slot1(t)] ----------------
__global__ void k_combine(float* __restrict__ out) {
    int i = blockIdx.x * blockDim.x + threadIdx.x;   // float4 index over T*D
    if (i >= T_TOK * (DDIM / 4)) return;
    int t = i >> 8;              // DDIM/4 = 256
    int c = i & 255;
    int s0 = g_slot[t * 2 + 0];
    int s1 = g_slot[t * 2 + 1];
    float4 a = ((const float4*)g_ys)[(size_t)s0 * 256 + c];
    float4 b = ((const float4*)g_ys)[(size_t)s1 * 256 + c];
    a.x += b.x; a.y += b.y; a.z += b.z; a.w += b.w;
    ((float4*)out)[i] = a;
}

// ---------------- launch --------------------------------------------------------
extern "C" void kernel_launch(void* const* d_in, const int* in_sizes, int n_in,
                              void* d_out, int out_size) {
    const float* x   = (const float*)d_in[0];
    const float* gw  = (const float*)d_in[1];
    const float* w1  = (const float*)d_in[2];
    const float* b1  = (const float*)d_in[3];
    const float* w2  = (const float*)d_in[4];
    const float* b2  = (const float*)d_in[5];
    const float* w3  = (const float*)d_in[6];
    const float* b3  = (const float*)d_in[7];
    float* out = (float*)d_out;

    k_init<<<1, 32>>>();
    k_gate<<<T_TOK / 4, 128>>>(x, gw);          // 4 warps/block, 1 warp/token
    k_prefix<<<1, 1>>>();
    k_scatter<<<T_TOK / 256, 256>>>();

    dim3 g12(HDIM / 128, T_TOK / 128, NEXP);    // (16, 64, 8)
    k_gemm_gather<0><<<g12, 256>>>(x, w1, b1, DDIM, HDIM);
    k_gemm_gather<1><<<g12, 256>>>(x, w2, b2, DDIM, HDIM);

    k_act<<<(MAXSLOTS * (HDIM / 4)) / 256, 256>>>();

    dim3 g3(DDIM / 128, T_TOK / 128, NEXP);     // (8, 64, 8)
    k_gemm_slab<<<g3, 256>>>(w3, b3);

    k_combine<<<(T_TOK * (DDIM / 4)) / 256, 256>>>(out);
}

// round 5
// speedup vs baseline: 3.3184x; 3.3184x over previous
#include <cuda_runtime.h>
#include <math.h>
#include <stdint.h>

// Problem constants (B=4, S=2048 -> T=8192; D=1024; H=2048; E=8; topk=2)
#define T_TOK 8192
#define DDIM  1024
#define HDIM  2048
#define NEXP  8
#define MAXSLOTS (T_TOK * 2)   // total routed slots is EXACTLY 2*T = 16384

// ---------------- static device scratch (no cudaMalloc allowed) ----------------
__device__ int   g_cnt[NEXP];
__device__ int   g_cur[NEXP];
__device__ int   g_off[NEXP + 1];
__device__ int   g_texp[T_TOK * 2];
__device__ float g_twt [T_TOK * 2];
__device__ int   g_tok [MAXSLOTS];
__device__ float g_wt  [MAXSLOTS];
__device__ int   g_slot[T_TOK * 2];

__device__ float g_xr [(size_t)T_TOK * DDIM];                 // tf32-rounded x
__device__ float g_wr1[(size_t)NEXP * HDIM * DDIM];           // tf32-rounded w1
__device__ float g_wr2[(size_t)NEXP * HDIM * DDIM];           // tf32-rounded w2
__device__ float g_wr3[(size_t)NEXP * DDIM * HDIM];           // tf32-rounded w3
__device__ float g_h1[((size_t)MAXSLOTS + 128) * HDIM];       // padded for GEMM3 A reads
__device__ float g_h2[(size_t)MAXSLOTS * HDIM];
__device__ float g_ys[(size_t)MAXSLOTS * DDIM];

// =============================== helpers ===================================
__device__ __forceinline__ uint32_t smem_u32(const void* p) {
    uint32_t a;
    asm("{ .reg .u64 t; cvta.to.shared.u64 t, %1; cvt.u32.u64 %0, t; }" : "=r"(a) : "l"(p));
    return a;
}
__device__ __forceinline__ float rtf(float x) {   // round-to-nearest tf32
    uint32_t u;
    asm("cvt.rna.tf32.f32 %0, %1;" : "=r"(u) : "f"(x));
    return __uint_as_float(u);
}
__device__ __forceinline__ void cp16(uint32_t dst, const void* src) {
    asm volatile("cp.async.cg.shared.global [%0], [%1], 16;" :: "r"(dst), "l"(src) : "memory");
}
#define CP_COMMIT()  asm volatile("cp.async.commit_group;" ::: "memory")
#define CP_WAIT1()   asm volatile("cp.async.wait_group 1;" ::: "memory")

// mma.sync m16n8k8 tf32 (arch-neutral tensor path; tcgen05 unavailable: ptxas target sm_103)
__device__ __forceinline__ void mma8(float* d, const float* a, const float* b) {
    asm volatile("mma.sync.aligned.m16n8k8.row.col.f32.tf32.tf32.f32 "
        "{%0,%1,%2,%3}, {%4,%5,%6,%7}, {%8,%9}, {%0,%1,%2,%3};"
        : "+f"(d[0]), "+f"(d[1]), "+f"(d[2]), "+f"(d[3])
        : "r"(__float_as_uint(a[0])), "r"(__float_as_uint(a[1])),
          "r"(__float_as_uint(a[2])), "r"(__float_as_uint(a[3])),
          "r"(__float_as_uint(b[0])), "r"(__float_as_uint(b[1])));
}

// =============================== routing kernels ================================
__global__ void k_init() {
    if (threadIdx.x < NEXP) g_cnt[threadIdx.x] = 0;
}

__global__ void k_gate(const float* __restrict__ x, const float* __restrict__ gw) {
    int warp = (blockIdx.x * blockDim.x + threadIdx.x) >> 5;
    int lane = threadIdx.x & 31;
    if (warp >= T_TOK) return;
    const float* xr = x + (size_t)warp * DDIM;

    float xv[32];
#pragma unroll
    for (int j = 0; j < 32; j++) xv[j] = xr[j * 32 + lane];

    float lg[NEXP];
#pragma unroll
    for (int e = 0; e < NEXP; e++) {
        const float* g = gw + e * DDIM;
        float s = 0.f;
#pragma unroll
        for (int j = 0; j < 32; j++) s += xv[j] * g[j * 32 + lane];
#pragma unroll
        for (int d = 16; d > 0; d >>= 1) s += __shfl_xor_sync(0xffffffffu, s, d);
        lg[e] = s;
    }
    int e0 = 0; float v0 = lg[0];
#pragma unroll
    for (int e = 1; e < NEXP; e++) if (lg[e] > v0) { v0 = lg[e]; e0 = e; }
    int e1 = (e0 == 0) ? 1 : 0; float v1 = lg[e1];
#pragma unroll
    for (int e = 0; e < NEXP; e++)
        if (e != e0 && lg[e] > v1) { v1 = lg[e]; e1 = e; }

    float w0 = 1.f / (1.f + expf(v1 - v0));
    float w1 = 1.f - w0;
    if (lane == 0) {
        atomicAdd(&g_cnt[e0], 1);
        atomicAdd(&g_cnt[e1], 1);
        g_texp[warp * 2 + 0] = e0;  g_texp[warp * 2 + 1] = e1;
        g_twt [warp * 2 + 0] = w0;  g_twt [warp * 2 + 1] = w1;
    }
}

__global__ void k_prefix() {
    int s = 0;
    for (int e = 0; e < NEXP; e++) { g_off[e] = s; g_cur[e] = s; s += g_cnt[e]; }
    g_off[NEXP] = s;
}

__global__ void k_scatter() {
    int t = blockIdx.x * blockDim.x + threadIdx.x;
    if (t >= T_TOK) return;
#pragma unroll
    for (int k = 0; k < 2; k++) {
        int e = g_texp[t * 2 + k];
        int s = atomicAdd(&g_cur[e], 1);
        g_tok[s] = t;
        g_wt[s]  = g_twt[t * 2 + k];
        g_slot[t * 2 + k] = s;
    }
}

// round src -> static tf32 buffer (template-selected dst)
template<int W>
__global__ void k_round(const float* __restrict__ src, int n4) {
    float* dst = (W == 0) ? g_wr1 : (W == 1) ? g_wr2 : (W == 2) ? g_wr3 : g_xr;
    int i = blockIdx.x * blockDim.x + threadIdx.x;
    if (i >= n4) return;
    float4 v = ((const float4*)src)[i];
    v.x = rtf(v.x); v.y = rtf(v.y); v.z = rtf(v.z); v.w = rtf(v.w);
    ((float4*)dst)[i] = v;
}

// h1 = round_tf32(h1 * silu(h2))
__global__ void k_act() {
    size_t i = (size_t)blockIdx.x * blockDim.x + threadIdx.x;
    if (i >= (size_t)MAXSLOTS * (HDIM / 4)) return;
    float4 a = ((const float4*)g_h1)[i];
    float4 b = ((const float4*)g_h2)[i];
    a.x = rtf(a.x * b.x / (1.f + expf(-b.x)));
    a.y = rtf(a.y * b.y / (1.f + expf(-b.y)));
    a.z = rtf(a.z * b.z / (1.f + expf(-b.z)));
    a.w = rtf(a.w * b.w / (1.f + expf(-b.w)));
    ((float4*)g_h1)[i] = a;
}

// =============================== tensor GEMM (mma.sync tf32) =====================
// MODE 0: h1[slot,n] = gather(xr)[slot,:] @ wr1[e][n,:] + b1   (K=1024, N=2048)
// MODE 1: h2[slot,n] = gather(xr)[slot,:] @ wr2[e][n,:] + b2   (K=1024, N=2048)
// MODE 2: ys[slot,n] = wt[slot]*(h1[slot,:] @ wr3[e][n,:] + b3) (K=2048, N=1024)
// CTA tile 128x256xk32, 512 thr, 16 warps of 64x32, 3-stage cp.async pipeline.
#define PADK     36            // 32 + 4 pad: bank = 4*row + k  -> conflict-free frags
#define A_F      (128 * PADK)  // 4608 floats
#define B_F      (256 * PADK)  // 9216 floats
#define STAGE_F  (A_F + B_F)   // 13824 floats = 55296 B
#define SOFF_F   384           // toks(128 int) + bias(256 f) before stages
#define GEMM_SMEM ((SOFF_F + 3 * STAGE_F) * 4)   // 167424 B

template<int MODE>
__global__ void __launch_bounds__(512) k_gemm_mma(const float* __restrict__ Bias)
{
    constexpr int Kd  = (MODE < 2) ? DDIM : HDIM;
    constexpr int Nd  = (MODE < 2) ? HDIM : DDIM;
    constexpr int NKB = Kd / 32;

    int e   = blockIdx.z;
    int cnt = g_cnt[e];
    int m0  = blockIdx.y * 128;
    if (m0 >= cnt) return;
    int off = g_off[e];
    int n0  = blockIdx.x * 256;

    const float* We  = ((MODE == 0) ? g_wr1 : (MODE == 1) ? g_wr2 : g_wr3) + (size_t)e * Nd * Kd;
    float*       dst = (MODE == 0) ? g_h1 : (MODE == 1) ? g_h2 : g_ys;

    extern __shared__ float smf[];
    int*   toks = (int*)smf;
    float* bias = smf + 128;
    uint32_t sb = smem_u32(smf);
    int tid = threadIdx.x;

    if (MODE < 2 && tid < 128) {
        int r = m0 + tid;
        toks[tid] = g_tok[off + (r < cnt ? r : 0)];
    }
    if (tid < 256) bias[tid] = Bias[(size_t)e * Nd + n0 + tid];
    __syncthreads();

    // -------- stage loader (cp.async): A 1024 chunks (2/thr), B 2048 chunks (4/thr)
    auto load_stage = [&](int i) {
        uint32_t S = sb + (SOFF_F + (i % 3) * STAGE_F) * 4;
        int k0 = i * 32;
#pragma unroll
        for (int c = 0; c < 2; c++) {
            int idx = tid + c * 512;
            int row = idx >> 3, kc = idx & 7;
            const float* src;
            if (MODE < 2) src = g_xr + (size_t)toks[row] * Kd + k0 + kc * 4;
            else          src = g_h1 + (size_t)(off + m0 + row) * Kd + k0 + kc * 4;
            cp16(S + (row * PADK + kc * 4) * 4, src);
        }
#pragma unroll
        for (int c = 0; c < 4; c++) {
            int idx = tid + c * 512;
            int row = idx >> 3, kc = idx & 7;
            const float* src = We + (size_t)(n0 + row) * Kd + k0 + kc * 4;
            cp16(S + (A_F + row * PADK + kc * 4) * 4, src);
        }
    };

    int w    = tid >> 5, lane = tid & 31;
    int g    = lane >> 2, tg = lane & 3;
    int wm   = (w >> 3) * 64;     // warp m-offset (2 rows of warps)
    int wn   = (w & 7) * 32;      // warp n-offset (8 cols of warps)

    float acc[4][4][4];
#pragma unroll
    for (int mt = 0; mt < 4; mt++)
#pragma unroll
        for (int nt = 0; nt < 4; nt++)
#pragma unroll
            for (int r = 0; r < 4; r++) acc[mt][nt][r] = 0.f;

    load_stage(0); CP_COMMIT();
    load_stage(1); CP_COMMIT();

    for (int j = 0; j < NKB; j++) {
        CP_WAIT1();
        __syncthreads();
        if (j + 2 < NKB) load_stage(j + 2);
        CP_COMMIT();

        const float* A = smf + SOFF_F + (j % 3) * STAGE_F;
        const float* B = A + A_F;
#pragma unroll
        for (int ks = 0; ks < 4; ks++) {
            int kb = ks * 8;
            float af[4][4], bf[4][2];
#pragma unroll
            for (int mt = 0; mt < 4; mt++) {
                const float* Ar = A + (wm + mt * 16 + g) * PADK + kb + tg;
                af[mt][0] = Ar[0];
                af[mt][1] = Ar[8 * PADK];
                af[mt][2] = Ar[4];
                af[mt][3] = Ar[8 * PADK + 4];
            }
#pragma unroll
            for (int nt = 0; nt < 4; nt++) {
                const float* Br = B + (wn + nt * 8 + g) * PADK + kb + tg;
                bf[nt][0] = Br[0];
                bf[nt][1] = Br[4];
            }
#pragma unroll
            for (int mt = 0; mt < 4; mt++)
#pragma unroll
                for (int nt = 0; nt < 4; nt++)
                    mma8(acc[mt][nt], af[mt], bf[nt]);
        }
    }

    // -------- epilogue: bias (+ routing weight for MODE 2), float2 stores --------
#pragma unroll
    for (int mt = 0; mt < 4; mt++) {
        int rl0 = wm + mt * 16 + g;       // local rows
        int rl1 = rl0 + 8;
        bool v0 = (m0 + rl0) < cnt;
        bool v1 = (m0 + rl1) < cnt;
        float wt0 = 1.f, wt1 = 1.f;
        if (MODE == 2) {
            wt0 = v0 ? g_wt[off + m0 + rl0] : 0.f;
            wt1 = v1 ? g_wt[off + m0 + rl1] : 0.f;
        }
        float* d0 = dst + (size_t)(off + m0 + rl0) * Nd + n0;
        float* d1 = dst + (size_t)(off + m0 + rl1) * Nd + n0;
#pragma unroll
        for (int nt = 0; nt < 4; nt++) {
            int cl = wn + nt * 8 + 2 * tg;
            float b0 = bias[cl], b1 = bias[cl + 1];
            if (v0) {
                float2 v = { wt0 * (acc[mt][nt][0] + b0), wt0 * (acc[mt][nt][1] + b1) };
                *(float2*)(d0 + cl) = v;
            }
            if (v1) {
                float2 v = { wt1 * (acc[mt][nt][2] + b0), wt1 * (acc[mt][nt][3] + b1) };
                *(float2*)(d1 + cl) = v;
            }
        }
    }
}

// ---------------- combine: out[t] = ys[slot0(t)] + ys[slot1(t)] ----------------
__global__ void k_combine(float* __restrict__ out) {
    int i = blockIdx.x * blockDim.x + threadIdx.x;
    if (i >= T_TOK * (DDIM / 4)) return;
    int t = i >> 8;
    int c = i & 255;
    int s0 = g_slot[t * 2 + 0];
    int s1 = g_slot[t * 2 + 1];
    float4 a = ((const float4*)g_ys)[(size_t)s0 * 256 + c];
    float4 b = ((const float4*)g_ys)[(size_t)s1 * 256 + c];
    a.x += b.x; a.y += b.y; a.z += b.z; a.w += b.w;
    ((float4*)out)[i] = a;
}

// ---------------- launch --------------------------------------------------------
extern "C" void kernel_launch(void* const* d_in, const int* in_sizes, int n_in,
                              void* d_out, int out_size) {
    const float* x   = (const float*)d_in[0];
    const float* gw  = (const float*)d_in[1];
    const float* w1  = (const float*)d_in[2];
    const float* b1  = (const float*)d_in[3];
    const float* w2  = (const float*)d_in[4];
    const float* b2  = (const float*)d_in[5];
    const float* w3  = (const float*)d_in[6];
    const float* b3  = (const float*)d_in[7];
    float* out = (float*)d_out;

    cudaFuncSetAttribute(k_gemm_mma<0>, cudaFuncAttributeMaxDynamicSharedMemorySize, GEMM_SMEM);
    cudaFuncSetAttribute(k_gemm_mma<1>, cudaFuncAttributeMaxDynamicSharedMemorySize, GEMM_SMEM);
    cudaFuncSetAttribute(k_gemm_mma<2>, cudaFuncAttributeMaxDynamicSharedMemorySize, GEMM_SMEM);

    const int W4 = NEXP * HDIM * DDIM / 4;       // 4194304
    const int X4 = T_TOK * DDIM / 4;             // 2097152
    k_round<0><<<W4 / 256, 256>>>(w1, W4);
    k_round<1><<<W4 / 256, 256>>>(w2, W4);
    k_round<2><<<W4 / 256, 256>>>(w3, W4);
    k_round<3><<<X4 / 256, 256>>>(x, X4);

    k_init<<<1, 32>>>();
    k_gate<<<T_TOK / 4, 128>>>(x, gw);
    k_prefix<<<1, 1>>>();
    k_scatter<<<T_TOK / 256, 256>>>();

    dim3 g12(HDIM / 256, T_TOK / 128, NEXP);     // (8, 64, 8)
    k_gemm_mma<0><<<g12, 512, GEMM_SMEM>>>(b1);
    k_gemm_mma<1><<<g12, 512, GEMM_SMEM>>>(b2);

    k_act<<<(MAXSLOTS * (HDIM / 4)) / 256, 256>>>();

    dim3 g3(DDIM / 256, T_TOK / 128, NEXP);      // (4, 64, 8)
    k_gemm_mma<2><<<g3, 512, GEMM_SMEM>>>(b3);

    k_combine<<<(T_TOK * (DDIM / 4)) / 256, 256>>>(out);
}